// round 2
// baseline (speedup 1.0000x reference)
#include <cuda_runtime.h>
#include <math.h>

// Problem shapes (fixed by the dataset)
#define BB 8
#define SS 2048
#define DD 512
#define HH 1024
#define CC 16

// Scratch (device globals: allocation-free per harness rules)
__device__ float g_r[BB * SS * HH];           // 64 MB  : r = x W1^T + b1
__device__ float g_s[(size_t)BB * SS * SS];   // 128 MB : scores / attn
__device__ float g_att[BB * SS * HH];         // 64 MB  : attended

// ---------------------------------------------------------------------------
// Tiled SGEMM: C[m,n] = sum_k A[m,k] * B(n,k or k,n)  (+bias[n])
// BM=BN=128, BK=8, 256 threads, 8x8 per-thread microtile.
// NT=true : B is row-major [N,K]  (C = A * B^T)
// NT=false: B is row-major [K,N]  (C = A * B)
// All dims assumed divisible by tile sizes (true for this problem).
// ---------------------------------------------------------------------------
template <bool NT>
__global__ __launch_bounds__(256) void sgemm_kernel(
    const float* __restrict__ A, const float* __restrict__ B,
    float* __restrict__ C, int M, int N, int K,
    size_t sA, size_t sB, size_t sC, const float* __restrict__ bias)
{
    constexpr int BM = 128, BN = 128, BK = 8;
    __shared__ float As[BK][BM];
    __shared__ float Bs[BK][BN];

    A += (size_t)blockIdx.z * sA + (size_t)blockIdx.y * BM * K;
    if (NT) B += (size_t)blockIdx.z * sB + (size_t)blockIdx.x * BN * K;
    else    B += (size_t)blockIdx.z * sB + (size_t)blockIdx.x * BN;
    C += (size_t)blockIdx.z * sC + (size_t)blockIdx.y * BM * N + (size_t)blockIdx.x * BN;

    const int tid = threadIdx.x;
    const int ty = tid >> 4;        // 0..15 (M microtile)
    const int tx = tid & 15;        // 0..15 (N microtile)

    // A/B(NT) tile loads: 128 rows x 8 k, 4 floats per thread
    const int arow = tid >> 1;
    const int acol = (tid & 1) * 4;
    // B(NN) tile loads: 8 k-rows x 128 n, 4 floats per thread
    const int brow = tid >> 5;
    const int bcol = (tid & 31) * 4;

    float acc[8][8] = {};

    for (int kt = 0; kt < K; kt += BK) {
        float4 av = *(const float4*)(A + (size_t)arow * K + kt + acol);
        As[acol + 0][arow] = av.x;
        As[acol + 1][arow] = av.y;
        As[acol + 2][arow] = av.z;
        As[acol + 3][arow] = av.w;
        if (NT) {
            float4 bv = *(const float4*)(B + (size_t)arow * K + kt + acol);
            Bs[acol + 0][arow] = bv.x;
            Bs[acol + 1][arow] = bv.y;
            Bs[acol + 2][arow] = bv.z;
            Bs[acol + 3][arow] = bv.w;
        } else {
            float4 bv = *(const float4*)(B + (size_t)(kt + brow) * N + bcol);
            *(float4*)&Bs[brow][bcol] = bv;
        }
        __syncthreads();

#pragma unroll
        for (int k = 0; k < BK; k++) {
            float a[8], b[8];
#pragma unroll
            for (int i = 0; i < 8; i++) a[i] = As[k][ty * 8 + i];
#pragma unroll
            for (int j = 0; j < 8; j++) b[j] = Bs[k][tx * 8 + j];
#pragma unroll
            for (int i = 0; i < 8; i++)
#pragma unroll
                for (int j = 0; j < 8; j++)
                    acc[i][j] = fmaf(a[i], b[j], acc[i][j]);
        }
        __syncthreads();
    }

#pragma unroll
    for (int i = 0; i < 8; i++) {
        int row = ty * 8 + i;
#pragma unroll
        for (int j = 0; j < 8; j++) {
            int col = tx * 8 + j;
            float v = acc[i][j];
            if (bias) v += bias[blockIdx.x * BN + col];
            C[(size_t)row * N + col] = v;
        }
    }
}

// ---------------------------------------------------------------------------
// Row softmax with max subtraction. One block (256 threads) per row of n.
// ---------------------------------------------------------------------------
__global__ __launch_bounds__(256) void softmax_rows(float* __restrict__ s, int n)
{
    float* row = s + (size_t)blockIdx.x * n;
    const int tid = threadIdx.x;
    const int lane = tid & 31, warp = tid >> 5;
    __shared__ float red[8];

    float m = -INFINITY;
    for (int j = tid; j < n; j += 256) m = fmaxf(m, row[j]);
#pragma unroll
    for (int o = 16; o; o >>= 1) m = fmaxf(m, __shfl_xor_sync(0xFFFFFFFFu, m, o));
    if (lane == 0) red[warp] = m;
    __syncthreads();
    m = red[0];
#pragma unroll
    for (int w = 1; w < 8; w++) m = fmaxf(m, red[w]);
    __syncthreads();

    float sum = 0.f;
    for (int j = tid; j < n; j += 256) {
        float e = __expf(row[j] - m);
        row[j] = e;
        sum += e;
    }
#pragma unroll
    for (int o = 16; o; o >>= 1) sum += __shfl_xor_sync(0xFFFFFFFFu, sum, o);
    if (lane == 0) red[warp] = sum;
    __syncthreads();
    sum = 0.f;
#pragma unroll
    for (int w = 0; w < 8; w++) sum += red[w];
    float inv = 1.f / sum;
    for (int j = tid; j < n; j += 256) row[j] *= inv;
}

// ---------------------------------------------------------------------------
// Fused: t = attended + r ; y = LN(t)*gamma+beta ; out = y W2^T + b2
// One block (256 threads) per row (16384 rows). C=16 classes.
// ---------------------------------------------------------------------------
__global__ __launch_bounds__(256) void ln_proj_kernel(
    const float* __restrict__ att, const float* __restrict__ r,
    const float* __restrict__ gamma, const float* __restrict__ beta,
    const float* __restrict__ W2, const float* __restrict__ b2,
    float* __restrict__ out)
{
    __shared__ float t[HH];
    __shared__ float red[16];
    __shared__ float part[CC * 8];

    const size_t m = blockIdx.x;
    const float* ar = att + m * HH;
    const float* rr = r + m * HH;
    const int tid = threadIdx.x;
    const int lane = tid & 31, warp = tid >> 5;

    float s = 0.f, s2 = 0.f;
    for (int h = tid; h < HH; h += 256) {
        float v = ar[h] + rr[h];
        t[h] = v;
        s += v;
        s2 += v * v;
    }
#pragma unroll
    for (int o = 16; o; o >>= 1) {
        s  += __shfl_xor_sync(0xFFFFFFFFu, s, o);
        s2 += __shfl_xor_sync(0xFFFFFFFFu, s2, o);
    }
    if (lane == 0) { red[warp] = s; red[8 + warp] = s2; }
    __syncthreads();
    s = 0.f; s2 = 0.f;
#pragma unroll
    for (int w = 0; w < 8; w++) { s += red[w]; s2 += red[8 + w]; }
    const float mu = s * (1.f / HH);
    const float var = s2 * (1.f / HH) - mu * mu;
    const float rstd = rsqrtf(var + 1e-5f);

    float acc[CC] = {};
    for (int h = tid; h < HH; h += 256) {
        float yv = (t[h] - mu) * rstd * gamma[h] + beta[h];
#pragma unroll
        for (int c = 0; c < CC; c++)
            acc[c] = fmaf(yv, W2[c * HH + h], acc[c]);
    }
#pragma unroll
    for (int c = 0; c < CC; c++) {
#pragma unroll
        for (int o = 16; o; o >>= 1)
            acc[c] += __shfl_xor_sync(0xFFFFFFFFu, acc[c], o);
    }
    if (lane == 0) {
#pragma unroll
        for (int c = 0; c < CC; c++) part[c * 8 + warp] = acc[c];
    }
    __syncthreads();
    if (tid < CC) {
        float v = 0.f;
#pragma unroll
        for (int w = 0; w < 8; w++) v += part[tid * 8 + w];
        out[m * CC + tid] = v + b2[tid];
    }
}

// ---------------------------------------------------------------------------
// Scratch pointers resolved ONCE on the first (non-captured) correctness call,
// so the graph-capture call contains kernel launches only.
// ---------------------------------------------------------------------------
struct Scratch {
    float *r, *s, *att;
    Scratch() {
        cudaGetSymbolAddress((void**)&r,   g_r);
        cudaGetSymbolAddress((void**)&s,   g_s);
        cudaGetSymbolAddress((void**)&att, g_att);
    }
};

extern "C" void kernel_launch(void* const* d_in, const int* in_sizes, int n_in,
                              void* d_out, int out_size)
{
    const float* x     = (const float*)d_in[0];
    const float* W1    = (const float*)d_in[1];
    const float* b1    = (const float*)d_in[2];
    const float* gamma = (const float*)d_in[3];
    const float* beta  = (const float*)d_in[4];
    const float* W2    = (const float*)d_in[5];
    const float* b2    = (const float*)d_in[6];
    float* out = (float*)d_out;

    static Scratch sc;   // initialized on first call (correctness run)
    float* r_p   = sc.r;
    float* s_p   = sc.s;
    float* att_p = sc.att;

    // 1) r = x W1^T + b1     [16384,512] x [1024,512]^T -> [16384,1024]
    {
        dim3 grid(HH / 128, (BB * SS) / 128, 1);
        sgemm_kernel<true><<<grid, 256>>>(x, W1, r_p, BB * SS, HH, DD, 0, 0, 0, b1);
    }
    // 2) scores = r r^T per batch   [2048,1024] x [2048,1024]^T -> [2048,2048]
    {
        dim3 grid(SS / 128, SS / 128, BB);
        sgemm_kernel<true><<<grid, 256>>>(r_p, r_p, s_p, SS, SS, HH,
                                          (size_t)SS * HH, (size_t)SS * HH,
                                          (size_t)SS * SS, nullptr);
    }
    // 3) softmax rows
    softmax_rows<<<BB * SS, 256>>>(s_p, SS);

    // 4) attended = P r per batch   [2048,2048] x [2048,1024] -> [2048,1024]
    {
        dim3 grid(HH / 128, SS / 128, BB);
        sgemm_kernel<false><<<grid, 256>>>(s_p, r_p, att_p, SS, HH, SS,
                                           (size_t)SS * SS, (size_t)SS * HH,
                                           (size_t)SS * HH, nullptr);
    }
    // 5) fused residual + LayerNorm + classifier
    ln_proj_kernel<<<BB * SS, 256>>>(att_p, r_p, gamma, beta, W2, b2, out);
}

// round 3
// speedup vs baseline: 2.5985x; 2.5985x over previous
#include <cuda_runtime.h>
#include <math.h>
#include <stdint.h>

// Problem shapes (fixed by the dataset)
#define BB 8
#define SS 2048
#define DD 512
#define HH 1024
#define CC 16

// Scratch (device globals: allocation-free per harness rules)
__device__ float g_r[BB * SS * HH];           // 64 MB  : r = x W1^T + b1
__device__ float g_s[(size_t)BB * SS * SS];   // 128 MB : scores / attn
__device__ float g_att[BB * SS * HH];         // 64 MB  : attended

__device__ __forceinline__ uint32_t f2tf32(float x) {
    uint32_t y;
    asm("cvt.rna.tf32.f32 %0, %1;" : "=r"(y) : "f"(x));
    return y;
}

__device__ __forceinline__ void mma_tf32(float* c, const uint32_t* a, const uint32_t* b) {
    asm volatile(
        "mma.sync.aligned.m16n8k8.row.col.f32.tf32.tf32.f32 "
        "{%0,%1,%2,%3}, {%4,%5,%6,%7}, {%8,%9}, {%0,%1,%2,%3};\n"
        : "+f"(c[0]), "+f"(c[1]), "+f"(c[2]), "+f"(c[3])
        : "r"(a[0]), "r"(a[1]), "r"(a[2]), "r"(a[3]), "r"(b[0]), "r"(b[1]));
}

// ---------------------------------------------------------------------------
// TF32 tensor-core GEMM: C[m,n] = sum_k A[m,k] * op(B)  (+bias[n])
// NT=true : B row-major [N,K]  (C = A B^T)     NT=false: B row-major [K,N]
// Block tile 128x128x16, 8 warps, warp tile 32x64 (2x8 m16n8k8 tiles).
// Smem stride 136 -> fragment reads are bank-conflict-free ((8k+m)%32 distinct).
// ---------------------------------------------------------------------------
#define KST 136
template <bool NT>
__global__ __launch_bounds__(256) void mma_gemm(
    const float* __restrict__ A, const float* __restrict__ B,
    float* __restrict__ C, int M, int N, int K,
    size_t sA, size_t sB, size_t sC, const float* __restrict__ bias)
{
    __shared__ uint32_t As[16][KST];
    __shared__ uint32_t Bs[16][KST];

    const int tid = threadIdx.x;
    const int warp = tid >> 5, lane = tid & 31;
    const int wm = (warp & 3) * 32;     // warp m offset in block tile
    const int wn = (warp >> 2) * 64;    // warp n offset
    const int g  = lane >> 2;           // groupID (0..7)
    const int tg = lane & 3;            // thread-in-group (0..3)

    A += (size_t)blockIdx.z * sA + (size_t)blockIdx.y * 128 * K;
    if (NT) B += (size_t)blockIdx.z * sB + (size_t)blockIdx.x * 128 * K;
    else    B += (size_t)blockIdx.z * sB + (size_t)blockIdx.x * 128;
    C += (size_t)blockIdx.z * sC + (size_t)blockIdx.y * 128 * N + (size_t)blockIdx.x * 128;

    // loader indices
    const int lr = tid >> 2, lc = (tid & 3) * 4;        // 64 rows x 16k per pass (x2)
    const int bkr = tid >> 5, bnc = (tid & 31) * 4;     // NN: 8 krows x 128n per pass (x2)

    float4 ra0, ra1, rb0, rb1;

    float acc[2][8][4];
#pragma unroll
    for (int i = 0; i < 2; i++)
#pragma unroll
        for (int j = 0; j < 8; j++)
#pragma unroll
            for (int q = 0; q < 4; q++) acc[i][j][q] = 0.f;

#define LOAD_TILES(kt)                                                          \
    {                                                                           \
        ra0 = *(const float4*)(A + (size_t)lr * K + (kt) + lc);                 \
        ra1 = *(const float4*)(A + (size_t)(lr + 64) * K + (kt) + lc);          \
        if (NT) {                                                               \
            rb0 = *(const float4*)(B + (size_t)lr * K + (kt) + lc);             \
            rb1 = *(const float4*)(B + (size_t)(lr + 64) * K + (kt) + lc);      \
        } else {                                                                \
            rb0 = *(const float4*)(B + (size_t)((kt) + bkr) * N + bnc);         \
            rb1 = *(const float4*)(B + (size_t)((kt) + bkr + 8) * N + bnc);     \
        }                                                                       \
    }

#define STORE_TILES()                                                           \
    {                                                                           \
        const float* pa0 = (const float*)&ra0;                                  \
        const float* pa1 = (const float*)&ra1;                                  \
        const float* pb0 = (const float*)&rb0;                                  \
        const float* pb1 = (const float*)&rb1;                                  \
        _Pragma("unroll")                                                       \
        for (int j = 0; j < 4; j++) {                                           \
            As[lc + j][lr]      = f2tf32(pa0[j]);                               \
            As[lc + j][lr + 64] = f2tf32(pa1[j]);                               \
        }                                                                       \
        if (NT) {                                                               \
            _Pragma("unroll")                                                   \
            for (int j = 0; j < 4; j++) {                                       \
                Bs[lc + j][lr]      = f2tf32(pb0[j]);                           \
                Bs[lc + j][lr + 64] = f2tf32(pb1[j]);                           \
            }                                                                   \
        } else {                                                                \
            _Pragma("unroll")                                                   \
            for (int j = 0; j < 4; j++) {                                       \
                Bs[bkr][bnc + j]     = f2tf32(pb0[j]);                          \
                Bs[bkr + 8][bnc + j] = f2tf32(pb1[j]);                          \
            }                                                                   \
        }                                                                       \
    }

#define COMPUTE()                                                               \
    {                                                                           \
        _Pragma("unroll")                                                       \
        for (int kk = 0; kk < 16; kk += 8) {                                    \
            uint32_t afr[2][4], bfr[8][2];                                      \
            _Pragma("unroll")                                                   \
            for (int mt = 0; mt < 2; mt++) {                                    \
                int m0 = wm + mt * 16;                                          \
                afr[mt][0] = As[kk + tg][m0 + g];                               \
                afr[mt][1] = As[kk + tg][m0 + g + 8];                           \
                afr[mt][2] = As[kk + tg + 4][m0 + g];                           \
                afr[mt][3] = As[kk + tg + 4][m0 + g + 8];                       \
            }                                                                   \
            _Pragma("unroll")                                                   \
            for (int nt = 0; nt < 8; nt++) {                                    \
                int n0 = wn + nt * 8;                                           \
                bfr[nt][0] = Bs[kk + tg][n0 + g];                               \
                bfr[nt][1] = Bs[kk + tg + 4][n0 + g];                           \
            }                                                                   \
            _Pragma("unroll")                                                   \
            for (int mt = 0; mt < 2; mt++)                                      \
                _Pragma("unroll")                                               \
                for (int nt = 0; nt < 8; nt++)                                  \
                    mma_tf32(acc[mt][nt], afr[mt], bfr[nt]);                    \
        }                                                                       \
    }

    const int ktiles = K / 16;
    LOAD_TILES(0);
    STORE_TILES();
    __syncthreads();
    for (int kt = 1; kt < ktiles; kt++) {
        LOAD_TILES(kt * 16);
        COMPUTE();
        __syncthreads();
        STORE_TILES();
        __syncthreads();
    }
    COMPUTE();

    // epilogue: C fragment c0,c1 at (g, 2tg), c2,c3 at (g+8, 2tg)
#pragma unroll
    for (int mt = 0; mt < 2; mt++) {
#pragma unroll
        for (int nt = 0; nt < 8; nt++) {
            int n0 = wn + nt * 8 + 2 * tg;
            int m0 = wm + mt * 16 + g;
            float2 v0 = make_float2(acc[mt][nt][0], acc[mt][nt][1]);
            float2 v1 = make_float2(acc[mt][nt][2], acc[mt][nt][3]);
            if (bias) {
                float bx0 = bias[blockIdx.x * 128 + n0];
                float bx1 = bias[blockIdx.x * 128 + n0 + 1];
                v0.x += bx0; v0.y += bx1;
                v1.x += bx0; v1.y += bx1;
            }
            *(float2*)(C + (size_t)m0 * N + n0) = v0;
            *(float2*)(C + (size_t)(m0 + 8) * N + n0) = v1;
        }
    }
#undef LOAD_TILES
#undef STORE_TILES
#undef COMPUTE
}

// ---------------------------------------------------------------------------
// Row softmax with max subtraction. One block (256 threads) per row of n.
// ---------------------------------------------------------------------------
__global__ __launch_bounds__(256) void softmax_rows(float* __restrict__ s, int n)
{
    float* row = s + (size_t)blockIdx.x * n;
    const int tid = threadIdx.x;
    const int lane = tid & 31, warp = tid >> 5;
    __shared__ float red[8];

    float m = -INFINITY;
    for (int j = tid; j < n; j += 256) m = fmaxf(m, row[j]);
#pragma unroll
    for (int o = 16; o; o >>= 1) m = fmaxf(m, __shfl_xor_sync(0xFFFFFFFFu, m, o));
    if (lane == 0) red[warp] = m;
    __syncthreads();
    m = red[0];
#pragma unroll
    for (int w = 1; w < 8; w++) m = fmaxf(m, red[w]);
    __syncthreads();

    float sum = 0.f;
    for (int j = tid; j < n; j += 256) {
        float e = __expf(row[j] - m);
        row[j] = e;
        sum += e;
    }
#pragma unroll
    for (int o = 16; o; o >>= 1) sum += __shfl_xor_sync(0xFFFFFFFFu, sum, o);
    if (lane == 0) red[warp] = sum;
    __syncthreads();
    sum = 0.f;
#pragma unroll
    for (int w = 0; w < 8; w++) sum += red[w];
    float inv = 1.f / sum;
    for (int j = tid; j < n; j += 256) row[j] *= inv;
}

// ---------------------------------------------------------------------------
// Fused: t = attended + r ; y = LN(t)*gamma+beta ; out = y W2^T + b2
// One block (256 threads) per row (16384 rows). C=16 classes.
// ---------------------------------------------------------------------------
__global__ __launch_bounds__(256) void ln_proj_kernel(
    const float* __restrict__ att, const float* __restrict__ r,
    const float* __restrict__ gamma, const float* __restrict__ beta,
    const float* __restrict__ W2, const float* __restrict__ b2,
    float* __restrict__ out)
{
    __shared__ float t[HH];
    __shared__ float red[16];
    __shared__ float part[CC * 8];

    const size_t m = blockIdx.x;
    const float* ar = att + m * HH;
    const float* rr = r + m * HH;
    const int tid = threadIdx.x;
    const int lane = tid & 31, warp = tid >> 5;

    float s = 0.f, s2 = 0.f;
    for (int h = tid; h < HH; h += 256) {
        float v = ar[h] + rr[h];
        t[h] = v;
        s += v;
        s2 += v * v;
    }
#pragma unroll
    for (int o = 16; o; o >>= 1) {
        s  += __shfl_xor_sync(0xFFFFFFFFu, s, o);
        s2 += __shfl_xor_sync(0xFFFFFFFFu, s2, o);
    }
    if (lane == 0) { red[warp] = s; red[8 + warp] = s2; }
    __syncthreads();
    s = 0.f; s2 = 0.f;
#pragma unroll
    for (int w = 0; w < 8; w++) { s += red[w]; s2 += red[8 + w]; }
    const float mu = s * (1.f / HH);
    const float var = s2 * (1.f / HH) - mu * mu;
    const float rstd = rsqrtf(var + 1e-5f);

    float acc[CC] = {};
    for (int h = tid; h < HH; h += 256) {
        float yv = (t[h] - mu) * rstd * gamma[h] + beta[h];
#pragma unroll
        for (int c = 0; c < CC; c++)
            acc[c] = fmaf(yv, W2[c * HH + h], acc[c]);
    }
#pragma unroll
    for (int c = 0; c < CC; c++) {
#pragma unroll
        for (int o = 16; o; o >>= 1)
            acc[c] += __shfl_xor_sync(0xFFFFFFFFu, acc[c], o);
    }
    if (lane == 0) {
#pragma unroll
        for (int c = 0; c < CC; c++) part[c * 8 + warp] = acc[c];
    }
    __syncthreads();
    if (tid < CC) {
        float v = 0.f;
#pragma unroll
        for (int w = 0; w < 8; w++) v += part[tid * 8 + w];
        out[m * CC + tid] = v + b2[tid];
    }
}

// ---------------------------------------------------------------------------
// Scratch pointers resolved ONCE on the first (non-captured) correctness call.
// ---------------------------------------------------------------------------
struct Scratch {
    float *r, *s, *att;
    Scratch() {
        cudaGetSymbolAddress((void**)&r,   g_r);
        cudaGetSymbolAddress((void**)&s,   g_s);
        cudaGetSymbolAddress((void**)&att, g_att);
    }
};

extern "C" void kernel_launch(void* const* d_in, const int* in_sizes, int n_in,
                              void* d_out, int out_size)
{
    const float* x     = (const float*)d_in[0];
    const float* W1    = (const float*)d_in[1];
    const float* b1    = (const float*)d_in[2];
    const float* gamma = (const float*)d_in[3];
    const float* beta  = (const float*)d_in[4];
    const float* W2    = (const float*)d_in[5];
    const float* b2    = (const float*)d_in[6];
    float* out = (float*)d_out;

    static Scratch sc;
    float* r_p   = sc.r;
    float* s_p   = sc.s;
    float* att_p = sc.att;

    // 1) r = x W1^T + b1     [16384,512] x [1024,512]^T -> [16384,1024]
    {
        dim3 grid(HH / 128, (BB * SS) / 128, 1);
        mma_gemm<true><<<grid, 256>>>(x, W1, r_p, BB * SS, HH, DD, 0, 0, 0, b1);
    }
    // 2) scores = r r^T per batch   [2048,1024] x [2048,1024]^T -> [2048,2048]
    {
        dim3 grid(SS / 128, SS / 128, BB);
        mma_gemm<true><<<grid, 256>>>(r_p, r_p, s_p, SS, SS, HH,
                                      (size_t)SS * HH, (size_t)SS * HH,
                                      (size_t)SS * SS, nullptr);
    }
    // 3) softmax rows
    softmax_rows<<<BB * SS, 256>>>(s_p, SS);

    // 4) attended = P r per batch   [2048,2048] x [2048,1024] -> [2048,1024]
    {
        dim3 grid(HH / 128, SS / 128, BB);
        mma_gemm<false><<<grid, 256>>>(s_p, r_p, att_p, SS, HH, SS,
                                       (size_t)SS * SS, (size_t)SS * HH,
                                       (size_t)SS * HH, nullptr);
    }
    // 5) fused residual + LayerNorm + classifier
    ln_proj_kernel<<<BB * SS, 256>>>(att_p, r_p, gamma, beta, W2, b2, out);
}